// round 6
// baseline (speedup 1.0000x reference)
#include <cuda_runtime.h>
#include <cstdint>

// MultiScaleDeformableAttention — GB300
// value:              (8, 22223, 8, 32)  float32
// sampling_locations: (8, 900, 8, 4, 4, 2) float32
// attention_weights:  (8, 900, 8, 4, 4) float32
// out:                (8, 900, 256) float32
//
// One warp per (b,q,h). lane = (g, cp): g = lane>>3 picks the point within a
// level, cp = lane&7 picks a float4 channel quad.
// Software-pipelined depth-2 over levels: issue level L's 4 unconditional
// LDG.128 (clamp index + zero weight for OOB), consume level L-1 while L's
// loads are in flight. Steady state: 8 float4 loads in flight (32 data regs)
// with regs capped at 51 -> 5 blocks/SM (40 warps).

#define BS  8
#define NQ  900
#define NH  8
#define DC  32
#define NL  4
#define NPT 4
#define NKEYS 22223
#define KS4 (NH * DC / 4)   // float4s per key = 64

struct TapDesc {
    int   o00, o10, o01, o11;
    float w00, w10, w01, w11;
};

__device__ __forceinline__ TapDesc make_desc(
    const float2* __restrict__ loc2, const float* __restrict__ aw,
    int warp, int g, int lvl, int H, int W, int start)
{
    const int li = (warp * NL + lvl) * NPT + g;
    const float2 l2 = __ldg(loc2 + li);
    const float w   = __ldg(aw + li);

    const float x = l2.x * (float)W - 0.5f;
    const float y = l2.y * (float)H - 0.5f;
    const float xf = floorf(x);
    const float yf = floorf(y);
    const int x0 = (int)xf;
    const int y0 = (int)yf;
    const int x1 = x0 + 1;
    const int y1 = y0 + 1;

    float wx1 = x - xf;
    float wx0 = 1.0f - wx1;
    float wy1 = y - yf;
    float wy0 = 1.0f - wy1;

    // branch-free OOB: clamp index, zero the corresponding edge weight
    if (x0 < 0 || x0 > W - 1) wx0 = 0.0f;
    if (x1 < 0 || x1 > W - 1) wx1 = 0.0f;
    if (y0 < 0 || y0 > H - 1) wy0 = 0.0f;
    if (y1 < 0 || y1 > H - 1) wy1 = 0.0f;
    const int x0c = min(max(x0, 0), W - 1);
    const int x1c = min(max(x1, 0), W - 1);
    const int y0c = min(max(y0, 0), H - 1);
    const int y1c = min(max(y1, 0), H - 1);

    TapDesc t;
    t.w00 = w * wx0 * wy0;
    t.w10 = w * wx1 * wy0;
    t.w01 = w * wx0 * wy1;
    t.w11 = w * wx1 * wy1;

    const int r0 = start + y0c * W;
    const int r1 = start + y1c * W;
    t.o00 = (r0 + x0c) * KS4;
    t.o10 = (r0 + x1c) * KS4;
    t.o01 = (r1 + x0c) * KS4;
    t.o11 = (r1 + x1c) * KS4;
    return t;
}

__device__ __forceinline__ void accumulate(
    float4& acc, const TapDesc& t,
    const float4& a, const float4& c, const float4& d, const float4& e)
{
    acc.x += a.x * t.w00 + c.x * t.w10 + d.x * t.w01 + e.x * t.w11;
    acc.y += a.y * t.w00 + c.y * t.w10 + d.y * t.w01 + e.y * t.w11;
    acc.z += a.z * t.w00 + c.z * t.w10 + d.z * t.w01 + e.z * t.w11;
    acc.w += a.w * t.w00 + c.w * t.w10 + d.w * t.w01 + e.w * t.w11;
}

__global__ __launch_bounds__(256, 5) void msda_kernel(
    const float* __restrict__ value,
    const float* __restrict__ loc,
    const float* __restrict__ aw,
    float* __restrict__ out)
{
    const int gtid = blockIdx.x * blockDim.x + threadIdx.x;
    const int warp = gtid >> 5;          // (b*NQ+q)*NH + h
    const int lane = gtid & 31;
    if (warp >= BS * NQ * NH) return;

    const int g  = lane >> 3;            // point within level (0..3)
    const int cp = lane & 7;             // channel quad (0..7)

    const int h  = warp & (NH - 1);
    const int b  = (warp >> 3) / NQ;

    const float4* __restrict__ v4 =
        (const float4*)value + ((size_t)(b * NKEYS) * NH + h) * (DC / 4) + cp;
    const float2* __restrict__ loc2 = (const float2*)loc;

    float4 acc = make_float4(0.f, 0.f, 0.f, 0.f);

    // ---- pipelined level loop, depth 2 ----
    // L0: desc + issue
    TapDesc t0 = make_desc(loc2, aw, warp, g, 0, 100, 167, 0);
    float4 a0 = __ldg(v4 + t0.o00);
    float4 c0 = __ldg(v4 + t0.o10);
    float4 d0 = __ldg(v4 + t0.o01);
    float4 e0 = __ldg(v4 + t0.o11);

    // L1: desc + issue
    TapDesc t1 = make_desc(loc2, aw, warp, g, 1, 50, 84, 16700);
    float4 a1 = __ldg(v4 + t1.o00);
    float4 c1 = __ldg(v4 + t1.o10);
    float4 d1 = __ldg(v4 + t1.o01);
    float4 e1 = __ldg(v4 + t1.o11);

    // consume L0, issue L2
    accumulate(acc, t0, a0, c0, d0, e0);
    TapDesc t2 = make_desc(loc2, aw, warp, g, 2, 25, 42, 20900);
    float4 a2 = __ldg(v4 + t2.o00);
    float4 c2 = __ldg(v4 + t2.o10);
    float4 d2 = __ldg(v4 + t2.o01);
    float4 e2 = __ldg(v4 + t2.o11);

    // consume L1, issue L3
    accumulate(acc, t1, a1, c1, d1, e1);
    TapDesc t3 = make_desc(loc2, aw, warp, g, 3, 13, 21, 21950);
    float4 a3 = __ldg(v4 + t3.o00);
    float4 c3 = __ldg(v4 + t3.o10);
    float4 d3 = __ldg(v4 + t3.o01);
    float4 e3 = __ldg(v4 + t3.o11);

    // drain
    accumulate(acc, t2, a2, c2, d2, e2);
    accumulate(acc, t3, a3, c3, d3, e3);

    // reduce the 4 point-groups (lanes cp, cp+8, cp+16, cp+24)
    #pragma unroll
    for (int m = 8; m <= 16; m <<= 1) {
        acc.x += __shfl_xor_sync(0xffffffffu, acc.x, m);
        acc.y += __shfl_xor_sync(0xffffffffu, acc.y, m);
        acc.z += __shfl_xor_sync(0xffffffffu, acc.z, m);
        acc.w += __shfl_xor_sync(0xffffffffu, acc.w, m);
    }

    if (g == 0) {
        ((float4*)out)[(size_t)warp * (DC / 4) + cp] = acc;
    }
}

extern "C" void kernel_launch(void* const* d_in, const int* in_sizes, int n_in,
                              void* d_out, int out_size)
{
    const float* value = (const float*)d_in[0];
    const float* loc   = (const float*)d_in[1];
    const float* aw    = (const float*)d_in[2];
    float* out         = (float*)d_out;

    const int nwarps  = BS * NQ * NH;                     // 57600
    const int threads = 256;
    const int blocks  = (nwarps * 32 + threads - 1) / threads;  // 7200
    msda_kernel<<<blocks, threads>>>(value, loc, aw, out);
}

// round 7
// speedup vs baseline: 1.0452x; 1.0452x over previous
#include <cuda_runtime.h>
#include <cstdint>

// MultiScaleDeformableAttention — GB300
// value:              (8, 22223, 8, 32)  float32
// sampling_locations: (8, 900, 8, 4, 4, 2) float32
// attention_weights:  (8, 900, 8, 4, 4) float32
// out:                (8, 900, 256) float32
//
// L2-throughput-bound (472MB of 128B-line gathers = LTS cap). This version
// exploits per-(b,h) key reuse (~2.6x) by pinning each (b,h) to one SM:
// grid = 128 CTAs x 1024 threads, CTA = (b, h, half). All queries of a
// (b,h,half) run on one SM, so the level-2 (131KB) and level-3 (34KB) value
// planes become L1-resident -> those taps stop hitting L2.
// Per-warp body identical to the best R4 kernel: lane=(g,cp), 16 tap
// descriptors computed branch-free, then 16 unconditional LDG.128 + FMA.

#define BS  8
#define NQ  900
#define NH  8
#define DC  32
#define NL  4
#define NPT 4
#define NKEYS 22223
#define KS4 (NH * DC / 4)   // float4s per key = 64
#define QHALF (NQ / 2)      // 450 queries per CTA

__global__ __launch_bounds__(1024, 1) void msda_kernel(
    const float* __restrict__ value,
    const float* __restrict__ loc,
    const float* __restrict__ aw,
    float* __restrict__ out)
{
    const int Hs[NL]     = {100, 50, 25, 13};
    const int Ws[NL]     = {167, 84, 42, 21};
    const int starts[NL] = {0, 16700, 20900, 21950};

    // CTA identity: (b, h, half)
    const int bh   = blockIdx.x >> 1;    // 0..63
    const int half = blockIdx.x & 1;     // 0..1
    const int b    = bh >> 3;
    const int h    = bh & (NH - 1);

    const int wid  = threadIdx.x >> 5;   // 0..31
    const int lane = threadIdx.x & 31;
    const int g  = lane >> 3;            // point within level (0..3)
    const int cp = lane & 7;             // channel quad (0..7)

    const float4* __restrict__ v4 =
        (const float4*)value + ((size_t)(b * NKEYS) * NH + h) * (DC / 4) + cp;
    const float2* __restrict__ loc2 = (const float2*)loc;

    for (int ql = wid; ql < QHALF; ql += 32) {
        const int q    = half * QHALF + ql;
        const int task = (b * NQ + q) * NH + h;   // original warp-task index

        // ---------------- Phase A: tap descriptors ----------------
        int   o00[NL], o10[NL], o01[NL], o11[NL];
        float w00[NL], w10[NL], w01[NL], w11[NL];

        #pragma unroll
        for (int lvl = 0; lvl < NL; ++lvl) {
            const int H = Hs[lvl];
            const int W = Ws[lvl];
            const int start = starts[lvl];

            const int li = (task * NL + lvl) * NPT + g;
            const float2 l2 = __ldg(loc2 + li);
            const float w   = __ldg(aw + li);

            const float x = l2.x * (float)W - 0.5f;
            const float y = l2.y * (float)H - 0.5f;
            const float xf = floorf(x);
            const float yf = floorf(y);
            const int x0 = (int)xf;
            const int y0 = (int)yf;
            const int x1 = x0 + 1;
            const int y1 = y0 + 1;

            float wx1 = x - xf;
            float wx0 = 1.0f - wx1;
            float wy1 = y - yf;
            float wy0 = 1.0f - wy1;

            // branch-free OOB: clamp index, zero the edge weight
            if (x0 < 0 || x0 > W - 1) wx0 = 0.0f;
            if (x1 < 0 || x1 > W - 1) wx1 = 0.0f;
            if (y0 < 0 || y0 > H - 1) wy0 = 0.0f;
            if (y1 < 0 || y1 > H - 1) wy1 = 0.0f;
            const int x0c = min(max(x0, 0), W - 1);
            const int x1c = min(max(x1, 0), W - 1);
            const int y0c = min(max(y0, 0), H - 1);
            const int y1c = min(max(y1, 0), H - 1);

            w00[lvl] = w * wx0 * wy0;
            w10[lvl] = w * wx1 * wy0;
            w01[lvl] = w * wx0 * wy1;
            w11[lvl] = w * wx1 * wy1;

            const int r0 = start + y0c * W;
            const int r1 = start + y1c * W;
            o00[lvl] = (r0 + x0c) * KS4;
            o10[lvl] = (r0 + x1c) * KS4;
            o01[lvl] = (r1 + x0c) * KS4;
            o11[lvl] = (r1 + x1c) * KS4;
        }

        // ---------------- Phase B: gather + accumulate ----------------
        float4 acc = make_float4(0.f, 0.f, 0.f, 0.f);

        #pragma unroll
        for (int lvl = 0; lvl < NL; ++lvl) {
            const float4 a = __ldg(v4 + o00[lvl]);
            const float4 c = __ldg(v4 + o10[lvl]);
            const float4 d = __ldg(v4 + o01[lvl]);
            const float4 e = __ldg(v4 + o11[lvl]);
            const float wa = w00[lvl], wc = w10[lvl], wd = w01[lvl], we = w11[lvl];

            acc.x += a.x * wa + c.x * wc + d.x * wd + e.x * we;
            acc.y += a.y * wa + c.y * wc + d.y * wd + e.y * we;
            acc.z += a.z * wa + c.z * wc + d.z * wd + e.z * we;
            acc.w += a.w * wa + c.w * wc + d.w * wd + e.w * we;
        }

        // reduce the 4 point-groups (lanes cp, cp+8, cp+16, cp+24)
        #pragma unroll
        for (int m = 8; m <= 16; m <<= 1) {
            acc.x += __shfl_xor_sync(0xffffffffu, acc.x, m);
            acc.y += __shfl_xor_sync(0xffffffffu, acc.y, m);
            acc.z += __shfl_xor_sync(0xffffffffu, acc.z, m);
            acc.w += __shfl_xor_sync(0xffffffffu, acc.w, m);
        }

        if (g == 0) {
            ((float4*)out)[(size_t)task * (DC / 4) + cp] = acc;
        }
    }
}

extern "C" void kernel_launch(void* const* d_in, const int* in_sizes, int n_in,
                              void* d_out, int out_size)
{
    const float* value = (const float*)d_in[0];
    const float* loc   = (const float*)d_in[1];
    const float* aw    = (const float*)d_in[2];
    float* out         = (float*)d_out;

    // 64 (b,h) pairs x 2 query-halves = 128 CTAs, one per SM
    msda_kernel<<<BS * NH * 2, 1024>>>(value, loc, aw, out);
}